// round 7
// baseline (speedup 1.0000x reference)
#include <cuda_runtime.h>
#include <cuda_fp16.h>
#include <cstdint>

#define N_USERS 100000
#define M_ITEMS 50000
#define N_NODES (N_USERS + M_ITEMS)        // 150000
#define N_EDGES 6000000
#define DIM 64
#define ROW_H2 (DIM / 2)                   // 32 half2 per node row
#define N_H2 ((size_t)N_NODES * ROW_H2)    // 4,800,000 half2

#define SCAN_B 1024
#define NB_SCAN ((N_NODES + SCAN_B - 1) / SCAN_B)   // 147

// ---- static scratch (no allocation allowed; zero-initialized at load) ------
__device__ __half2  g_b0[N_H2];        // 19.2 MB  h after 0 hops (quantized input)
__device__ __half2  g_b1[N_H2];        // 19.2 MB  h after 1 hop
__device__ __half2  g_b2[N_H2];        // 19.2 MB  h after 2 hops
__device__ uint32_t g_edges[N_EDGES];  // 24 MB    packed (src<<14 | val_q14), sorted by dst
__device__ int      g_cnt[N_NODES];    // INVARIANT: == 0 at kernel_launch entry
                                       // (zeroed by final spmm of previous run;
                                       //  zero-init on first run)
__device__ int      g_off[N_NODES];
__device__ int      g_pos[N_NODES];

// ---------------------------------------------------------------------------
// Fused: b0 = fp16(concat(user_emb, item_emb))  AND  histogram of dst.
// Requires g_cnt == 0 at entry (see invariant above).
// ---------------------------------------------------------------------------
__global__ void init_hist_kernel(const float* __restrict__ user_emb,
                                 const float* __restrict__ item_emb,
                                 const int*   __restrict__ dst) {
    size_t i = (size_t)blockIdx.x * blockDim.x + threadIdx.x;
    if (i < N_H2) {
        size_t user2 = (size_t)N_USERS * ROW_H2;
        float2 v = (i < user2) ? ((const float2*)user_emb)[i]
                               : ((const float2*)item_emb)[i - user2];
        g_b0[i] = __floats2half2_rn(v.x, v.y);
    }
    if (i < N_EDGES) atomicAdd(&g_cnt[dst[i]], 1);
}

// ---------------------------------------------------------------------------
// Exclusive scan of g_cnt -> g_off, g_pos (single kernel).
// Block b computes its base by directly summing g_cnt[0 .. b*SCAN_B)
// (coalesced; <= 11M total reads across the grid, ~2us).
// ---------------------------------------------------------------------------
__global__ void scan_kernel() {
    __shared__ int sm[SCAN_B];
    int b = blockIdx.x;

    // block base = sum of all counts before this block's range
    int acc = 0;
    int lim = b * SCAN_B;
    if (lim > N_NODES) lim = N_NODES;
    for (int k = threadIdx.x; k < lim; k += SCAN_B) acc += g_cnt[k];
    sm[threadIdx.x] = acc;
    __syncthreads();
    for (int s = SCAN_B / 2; s > 0; s >>= 1) {
        if (threadIdx.x < s) sm[threadIdx.x] += sm[threadIdx.x + s];
        __syncthreads();
    }
    int base = sm[0];
    __syncthreads();

    // local inclusive scan (Hillis-Steele) -> exclusive offsets
    int idx = b * SCAN_B + threadIdx.x;
    int x = (idx < N_NODES) ? g_cnt[idx] : 0;
    sm[threadIdx.x] = x;
    __syncthreads();
    for (int o = 1; o < SCAN_B; o <<= 1) {
        int t = (threadIdx.x >= o) ? sm[threadIdx.x - o] : 0;
        __syncthreads();
        sm[threadIdx.x] += t;
        __syncthreads();
    }
    if (idx < N_NODES) {
        int excl = sm[threadIdx.x] - x + base;
        g_off[idx] = excl;
        g_pos[idx] = excl;
    }
}

// ---------------------------------------------------------------------------
// Counting-sort edges by dst into packed 4B records:
//   rec = (src << 14) | round(val * 16384)   (val in [0,1); decode scale 2^-14)
// ---------------------------------------------------------------------------
__global__ void scatter_kernel(const int* __restrict__ src,
                               const int* __restrict__ dst,
                               const float* __restrict__ val) {
    int e = blockIdx.x * blockDim.x + threadIdx.x;
    if (e < N_EDGES) {
        uint32_t q = __float2uint_rn(val[e] * 16384.0f);
        if (q > 16383u) q = 16383u;
        uint32_t rec = ((uint32_t)src[e] << 14) | q;
        int p = atomicAdd(&g_pos[dst[e]], 1);
        g_edges[p] = rec;
    }
}

// ---------------------------------------------------------------------------
// CSR SpMM: one warp per destination node, one half2 (2 dims) per lane.
// Packed edges staged 32/batch: staging lane decodes once (src*32, f32 val)
// into smem; inner loop does LDS.64 broadcast + 128B coalesced row gather.
// f32 accumulation in registers. FINAL fuses out = (b0+b1+b2+h3)*0.25 and
// restores the g_cnt == 0 invariant for the next execution.
// ---------------------------------------------------------------------------
template<bool FINAL>
__global__ __launch_bounds__(256)
void spmm_csr_kernel(const __half2* __restrict__ hin,
                     __half2* __restrict__ hout,
                     float* __restrict__ out) {
    __shared__ int2 sm_ed[8][32];
    int wl   = threadIdx.x >> 5;
    int node = blockIdx.x * (blockDim.x >> 5) + wl;
    int lane = threadIdx.x & 31;
    if (node >= N_NODES) return;

    int start = g_off[node];
    int n     = g_cnt[node];

    const float DEC = 1.0f / 16384.0f;     // exact power of 2
    float2 s = make_float2(0.f, 0.f);
    int i = 0;
    for (; i + 32 <= n; i += 32) {
        uint32_t rec = __ldg(&g_edges[start + i + lane]);
        sm_ed[wl][lane] = make_int2((int)(rec >> 14) * ROW_H2,
                                    __float_as_int((float)(rec & 16383u) * DEC));
        __syncwarp();
        #pragma unroll 8
        for (int j = 0; j < 32; j++) {
            int2 e = sm_ed[wl][j];
            float  v = __int_as_float(e.y);
            float2 x = __half22float2(__ldg(&hin[e.x + lane]));
            s.x += v * x.x;
            s.y += v * x.y;
        }
        __syncwarp();
    }
    int rem = n - i;
    if (rem > 0) {
        int2 ed = make_int2(0, 0);
        if (lane < rem) {
            uint32_t rec = __ldg(&g_edges[start + i + lane]);
            ed = make_int2((int)(rec >> 14) * ROW_H2,
                           __float_as_int((float)(rec & 16383u) * DEC));
        }
        sm_ed[wl][lane] = ed;
        __syncwarp();
        for (int j = 0; j < rem; j++) {
            int2 e = sm_ed[wl][j];
            float  v = __int_as_float(e.y);
            float2 x = __half22float2(__ldg(&hin[e.x + lane]));
            s.x += v * x.x;
            s.y += v * x.y;
        }
    }

    size_t o = (size_t)node * ROW_H2 + lane;
    if (!FINAL) {
        hout[o] = __floats2half2_rn(s.x, s.y);
    } else {
        float2 a0 = __half22float2(g_b0[o]);
        float2 a1 = __half22float2(g_b1[o]);
        float2 a2 = __half22float2(hin[o]);   // hin == g_b2 in the final layer
        float2 r;
        r.x = (a0.x + a1.x + a2.x + s.x) * 0.25f;
        r.y = (a0.y + a1.y + a2.y + s.y) * 0.25f;
        ((float2*)out)[o] = r;
        if (lane == 0) g_cnt[node] = 0;       // restore invariant for next run
    }
}

// ---------------------------------------------------------------------------
extern "C" void kernel_launch(void* const* d_in, const int* in_sizes, int n_in,
                              void* d_out, int out_size) {
    const float* user_emb = (const float*)d_in[0];
    const float* item_emb = (const float*)d_in[1];
    const int*   edge_src = (const int*)d_in[2];
    const int*   edge_dst = (const int*)d_in[3];
    const float* edge_val = (const float*)d_in[4];
    float* out = (float*)d_out;

    __half2 *b0, *b1, *b2;
    cudaGetSymbolAddress((void**)&b0, g_b0);
    cudaGetSymbolAddress((void**)&b1, g_b1);
    cudaGetSymbolAddress((void**)&b2, g_b2);

    const int TB = 256;
    const int grid_edge = (N_EDGES + TB - 1) / TB;                 // covers N_H2 too
    const int grid_spmm = (N_NODES * 32 + TB - 1) / TB;            // 1 warp / node

    // 0: fused init + dst histogram (g_cnt is 0 on entry by invariant)
    init_hist_kernel<<<grid_edge, TB>>>(user_emb, item_emb, edge_dst);
    // 1: exclusive scan -> g_off, g_pos
    scan_kernel<<<NB_SCAN, SCAN_B>>>();
    // 2: counting-sort edges by dst (packed 4B records)
    scatter_kernel<<<grid_edge, TB>>>(edge_src, edge_dst, edge_val);

    // 3: Layer 1: b0 -> b1
    spmm_csr_kernel<false><<<grid_spmm, TB>>>(b0, b1, nullptr);
    // 4: Layer 2: b1 -> b2
    spmm_csr_kernel<false><<<grid_spmm, TB>>>(b1, b2, nullptr);
    // 5: Layer 3: b2 -> (h3 on the fly), out = (b0+b1+b2+h3) * 0.25, reset g_cnt
    spmm_csr_kernel<true><<<grid_spmm, TB>>>(b2, nullptr, out);
}

// round 8
// speedup vs baseline: 1.3603x; 1.3603x over previous
#include <cuda_runtime.h>
#include <cuda_fp16.h>
#include <cstdint>

#define N_USERS 100000
#define M_ITEMS 50000
#define N_NODES (N_USERS + M_ITEMS)        // 150000
#define N_EDGES 6000000
#define DIM 64
#define ROW_H2 (DIM / 2)                   // 32 half2 per node row
#define ROW_U2 (DIM / 4)                   // 16 uint2 (4 halfs) per node row
#define N_H2 ((size_t)N_NODES * ROW_H2)    // 4,800,000 half2

#define SCAN_B 1024
#define NB_SCAN ((N_NODES + SCAN_B - 1) / SCAN_B)   // 147

// ---- static scratch (no allocation allowed; zero-initialized at load) ------
__device__ __half2 g_b0[N_H2];       // 19.2 MB  h after 0 hops (quantized input)
__device__ __half2 g_b1[N_H2];       // 19.2 MB  h after 1 hop
__device__ __half2 g_b2[N_H2];       // 19.2 MB  h after 2 hops
__device__ int2    g_edges[N_EDGES]; // 48 MB    (src*ROW_U2, val_bits) sorted by dst
__device__ int     g_cnt[N_NODES];   // INVARIANT: == 0 at kernel_launch entry
                                     // (zeroed by final spmm of previous run;
                                     //  zero-init on first run)
__device__ int     g_off[N_NODES];
__device__ int     g_pos[N_NODES];

// ---------------------------------------------------------------------------
// Fused: b0 = fp16(concat(user_emb, item_emb))  AND  histogram of dst.
// Requires g_cnt == 0 at entry (see invariant above).
// ---------------------------------------------------------------------------
__global__ void init_hist_kernel(const float* __restrict__ user_emb,
                                 const float* __restrict__ item_emb,
                                 const int*   __restrict__ dst) {
    size_t i = (size_t)blockIdx.x * blockDim.x + threadIdx.x;
    if (i < N_H2) {
        size_t user2 = (size_t)N_USERS * ROW_H2;
        float2 v = (i < user2) ? ((const float2*)user_emb)[i]
                               : ((const float2*)item_emb)[i - user2];
        g_b0[i] = __floats2half2_rn(v.x, v.y);
    }
    if (i < N_EDGES) atomicAdd(&g_cnt[dst[i]], 1);
}

// ---------------------------------------------------------------------------
// Exclusive scan of g_cnt -> g_off, g_pos (single kernel).
// Block b computes its base by directly summing g_cnt[0 .. b*SCAN_B).
// ---------------------------------------------------------------------------
__global__ void scan_kernel() {
    __shared__ int sm[SCAN_B];
    int b = blockIdx.x;

    int acc = 0;
    int lim = b * SCAN_B;
    if (lim > N_NODES) lim = N_NODES;
    for (int k = threadIdx.x; k < lim; k += SCAN_B) acc += g_cnt[k];
    sm[threadIdx.x] = acc;
    __syncthreads();
    for (int s = SCAN_B / 2; s > 0; s >>= 1) {
        if (threadIdx.x < s) sm[threadIdx.x] += sm[threadIdx.x + s];
        __syncthreads();
    }
    int base = sm[0];
    __syncthreads();

    int idx = b * SCAN_B + threadIdx.x;
    int x = (idx < N_NODES) ? g_cnt[idx] : 0;
    sm[threadIdx.x] = x;
    __syncthreads();
    for (int o = 1; o < SCAN_B; o <<= 1) {
        int t = (threadIdx.x >= o) ? sm[threadIdx.x - o] : 0;
        __syncthreads();
        sm[threadIdx.x] += t;
        __syncthreads();
    }
    if (idx < N_NODES) {
        int excl = sm[threadIdx.x] - x + base;
        g_off[idx] = excl;
        g_pos[idx] = excl;
    }
}

// ---------------------------------------------------------------------------
// Counting-sort edges by dst: record = (src * ROW_U2, f32 val bits).
// ---------------------------------------------------------------------------
__global__ void scatter_kernel(const int* __restrict__ src,
                               const int* __restrict__ dst,
                               const float* __restrict__ val) {
    int e = blockIdx.x * blockDim.x + threadIdx.x;
    if (e < N_EDGES) {
        int p = atomicAdd(&g_pos[dst[e]], 1);
        g_edges[p] = make_int2(src[e] * ROW_U2, __float_as_int(val[e]));
    }
}

// ---------------------------------------------------------------------------
// CSR SpMM, pair scheme: one warp per destination node; lanes 0-15 process
// even edges, lanes 16-31 odd edges; each lane owns 4 dims (uint2 = 2 half2).
// Per inner iteration 2 edges are consumed: 1 LDS.64 + 1 LDG.64 + 4 cvt +
// 4 FFMA per lane. f32 accumulation, cross-half combine via SHFL.XOR(16).
// FINAL fuses out = (b0+b1+b2+h3)*0.25 and restores g_cnt == 0.
// ---------------------------------------------------------------------------
template<bool FINAL>
__global__ __launch_bounds__(256)
void spmm_csr_kernel(const __half2* __restrict__ hin,
                     __half2* __restrict__ hout,
                     float* __restrict__ out) {
    __shared__ int2 sm_ed[8][32];
    int wl   = threadIdx.x >> 5;
    int node = blockIdx.x * (blockDim.x >> 5) + wl;
    int lane = threadIdx.x & 31;
    if (node >= N_NODES) return;

    int start = g_off[node];
    int n     = g_cnt[node];
    int half  = lane >> 4;       // which edge of the pair this lane serves
    int hoff  = lane & 15;       // which uint2 (4 dims) of the row

    const uint2* __restrict__ hp = (const uint2*)hin;

    float s0 = 0.f, s1 = 0.f, s2 = 0.f, s3 = 0.f;
    int i = 0;
    for (; i + 32 <= n; i += 32) {
        sm_ed[wl][lane] = __ldg(&g_edges[start + i + lane]);
        __syncwarp();
        #pragma unroll
        for (int j = 0; j < 16; j++) {
            int2 e  = sm_ed[wl][2 * j + half];
            float v = __int_as_float(e.y);
            uint2 x = __ldg(&hp[e.x + hoff]);
            float2 fa = __half22float2(*(const __half2*)&x.x);
            float2 fb = __half22float2(*(const __half2*)&x.y);
            s0 += v * fa.x; s1 += v * fa.y;
            s2 += v * fb.x; s3 += v * fb.y;
        }
        __syncwarp();
    }
    int rem = n - i;
    if (rem > 0) {
        int2 ed = make_int2(0, 0);                      // zero-pad (v=0)
        if (lane < rem) ed = __ldg(&g_edges[start + i + lane]);
        sm_ed[wl][lane] = ed;
        __syncwarp();
        int npair = (rem + 1) >> 1;
        for (int j = 0; j < npair; j++) {
            int2 e  = sm_ed[wl][2 * j + half];
            float v = __int_as_float(e.y);
            uint2 x = __ldg(&hp[e.x + hoff]);
            float2 fa = __half22float2(*(const __half2*)&x.x);
            float2 fb = __half22float2(*(const __half2*)&x.y);
            s0 += v * fa.x; s1 += v * fa.y;
            s2 += v * fb.x; s3 += v * fb.y;
        }
    }

    // combine the two half-warps (even-edge sums + odd-edge sums)
    s0 += __shfl_xor_sync(0xffffffffu, s0, 16);
    s1 += __shfl_xor_sync(0xffffffffu, s1, 16);
    s2 += __shfl_xor_sync(0xffffffffu, s2, 16);
    s3 += __shfl_xor_sync(0xffffffffu, s3, 16);

    if (lane < 16) {
        size_t o = (size_t)node * ROW_U2 + hoff;        // uint2 / float4 index
        if (!FINAL) {
            __half2 ha = __floats2half2_rn(s0, s1);
            __half2 hb = __floats2half2_rn(s2, s3);
            uint2 r;
            r.x = *(const unsigned int*)&ha;
            r.y = *(const unsigned int*)&hb;
            ((uint2*)hout)[o] = r;
        } else {
            uint2 p0 = ((const uint2*)g_b0)[o];
            uint2 p1 = ((const uint2*)g_b1)[o];
            uint2 p2 = ((const uint2*)hin)[o];          // hin == g_b2 here
            float2 a0 = __half22float2(*(const __half2*)&p0.x);
            float2 b0_ = __half22float2(*(const __half2*)&p0.y);
            float2 a1 = __half22float2(*(const __half2*)&p1.x);
            float2 b1_ = __half22float2(*(const __half2*)&p1.y);
            float2 a2 = __half22float2(*(const __half2*)&p2.x);
            float2 b2_ = __half22float2(*(const __half2*)&p2.y);
            float4 r;
            r.x = (a0.x + a1.x + a2.x + s0) * 0.25f;
            r.y = (a0.y + a1.y + a2.y + s1) * 0.25f;
            r.z = (b0_.x + b1_.x + b2_.x + s2) * 0.25f;
            r.w = (b0_.y + b1_.y + b2_.y + s3) * 0.25f;
            ((float4*)out)[o] = r;
        }
    }
    if (FINAL && lane == 0) g_cnt[node] = 0;            // restore invariant
}

// ---------------------------------------------------------------------------
extern "C" void kernel_launch(void* const* d_in, const int* in_sizes, int n_in,
                              void* d_out, int out_size) {
    const float* user_emb = (const float*)d_in[0];
    const float* item_emb = (const float*)d_in[1];
    const int*   edge_src = (const int*)d_in[2];
    const int*   edge_dst = (const int*)d_in[3];
    const float* edge_val = (const float*)d_in[4];
    float* out = (float*)d_out;

    __half2 *b0, *b1, *b2;
    cudaGetSymbolAddress((void**)&b0, g_b0);
    cudaGetSymbolAddress((void**)&b1, g_b1);
    cudaGetSymbolAddress((void**)&b2, g_b2);

    const int TB = 256;
    const int grid_edge = (N_EDGES + TB - 1) / TB;                 // covers N_H2 too
    const int grid_spmm = (N_NODES * 32 + TB - 1) / TB;            // 1 warp / node

    // 0: fused init + dst histogram (g_cnt is 0 on entry by invariant)
    init_hist_kernel<<<grid_edge, TB>>>(user_emb, item_emb, edge_dst);
    // 1: exclusive scan -> g_off, g_pos
    scan_kernel<<<NB_SCAN, SCAN_B>>>();
    // 2: counting-sort edges by dst (int2 records, f32 weights)
    scatter_kernel<<<grid_edge, TB>>>(edge_src, edge_dst, edge_val);

    // 3: Layer 1: b0 -> b1
    spmm_csr_kernel<false><<<grid_spmm, TB>>>(b0, b1, nullptr);
    // 4: Layer 2: b1 -> b2
    spmm_csr_kernel<false><<<grid_spmm, TB>>>(b1, b2, nullptr);
    // 5: Layer 3: b2 -> (h3 on the fly), out = (b0+b1+b2+h3) * 0.25, reset g_cnt
    spmm_csr_kernel<true><<<grid_spmm, TB>>>(b2, nullptr, out);
}